// round 12
// baseline (speedup 1.0000x reference)
#include <cuda_runtime.h>
#include <cuda_fp16.h>
#include <math.h>
#include <stdint.h>

#define BB 8
#define NN 4096
#define DD 512
#define TD 256
#define TOK (BB*NN)
#define SCALE_F 0.0625f

// ---------------- static scratch ----------------
__device__ __align__(16) __half g_xh[2][(size_t)TOK*DD];     // x fp16 (I, M)
__device__ __align__(16) __half g_raw16[4][(size_t)TOK*DD];  // proj out + bias, fp16
__device__ __align__(16) __half g_ph[4][(size_t)TOK*DD];     // normalized q/k fp16 [qI,qM,kI,kM]
__device__ __align__(16) __half g_Wth[4][DD*DD];             // W^T fp16 [mat][n][k]
__device__ __align__(16) __half g_Wch[BB][TD*2048];          // combined W^T fp16 [b][n][k]
__device__ float g_fwT[TD*DD];                               // f_w^T [n][e]
__device__ float g_PFt[4][TD*DD];                            // (p_i@f_w)^T [n][k]
__device__ float g_acc[BB*2*513];
__device__ float g_cvec[TD];

// ---------------- helpers ----------------
__device__ __forceinline__ uint32_t smem_u32(const void* p) {
    uint32_t a;
    asm("{ .reg .u64 t; cvta.to.shared.u64 t, %1; cvt.u32.u64 %0, t; }" : "=r"(a) : "l"(p));
    return a;
}
__device__ __forceinline__ void cp16(uint32_t s, const void* g) {
    asm volatile("cp.async.cg.shared.global [%0], [%1], 16;" :: "r"(s), "l"(g));
}
__device__ __forceinline__ void cp_commit() { asm volatile("cp.async.commit_group;"); }
__device__ __forceinline__ void cp_wait1()  { asm volatile("cp.async.wait_group 1;"); }
__device__ __forceinline__ void cp_wait0()  { asm volatile("cp.async.wait_group 0;"); }
__device__ __forceinline__ void ldsm4(uint32_t* r, uint32_t addr) {
    asm volatile("ldmatrix.sync.aligned.m8n8.x4.shared.b16 {%0,%1,%2,%3}, [%4];"
        : "=r"(r[0]), "=r"(r[1]), "=r"(r[2]), "=r"(r[3]) : "r"(addr));
}
__device__ __forceinline__ void mma_f16(float* c, const uint32_t* a, uint32_t b0, uint32_t b1) {
    asm volatile("mma.sync.aligned.m16n8k16.row.col.f32.f16.f16.f32 "
        "{%0,%1,%2,%3}, {%4,%5,%6,%7}, {%8,%9}, {%0,%1,%2,%3};"
        : "+f"(c[0]), "+f"(c[1]), "+f"(c[2]), "+f"(c[3])
        : "r"(a[0]), "r"(a[1]), "r"(a[2]), "r"(a[3]), "r"(b0), "r"(b1));
}

// SMEM per buffer: A 16KB + B 16KB = 32KB; ring of 3 = 96KB
#define BUFSZ 32768
#define SMEM_TOTAL 98304

// ---------------- MMA GEMM (MODE 0 = proj -> raw16 (+bias); MODE 1 = final -> out) ----
// MODE 0 grid: 4096 flat; bx&3=which, (bx>>2)&3=ntile, bx>>4=tokblk (A sharers adjacent)
// MODE 1 grid: 512 flat;  bx&1=ntile, bx>>1=tokblk
template<int MODE>
__global__ void __launch_bounds__(256) mma_gemm(
    const float* __restrict__ bqI, const float* __restrict__ bqM,
    const float* __restrict__ bkI, const float* __restrict__ bkM,
    float* __restrict__ outp)
{
    extern __shared__ char smem[];
    const uint32_t sb = smem_u32(smem);
    __shared__ float sbias[128];

    const int tid = threadIdx.x, wid = tid >> 5, lane = tid & 31;
    const int bx = blockIdx.x;
    const int which = (MODE == 0) ? (bx & 3) : 0;
    const int n0    = (MODE == 0) ? (((bx >> 2) & 3) * 128) : ((bx & 1) * 128);
    const int tok0  = (MODE == 0) ? ((bx >> 4) * 128) : ((bx >> 1) * 128);
    const int batch = tok0 >> 12;
    const int NC = (MODE == 0) ? 8 : 32;

    if (MODE == 0) {
        const float* bias = (which==0)?bqI:(which==1)?bqM:(which==2)?bkI:bkM;
        if (tid < 128) sbias[tid] = bias[n0 + tid];
    } else {
        if (tid < 128) sbias[tid] = g_cvec[n0 + tid];
    }

    const int xsel = which & 1;

    // ---- issue chunk c (Kc=64) into ring buffer via cp.async ----
    auto issue = [&](int c, int buf) {
        uint32_t abase = sb + buf*BUFSZ;
        uint32_t bbase = abase + 16384;
        // A: 128 rows x 64 halves (8 x 16B per row)
        #pragma unroll
        for (int it = 0; it < 4; it++) {
            int v = it*256 + tid;
            int r = v >> 3, u = v & 7;
            const __half* src;
            if (MODE == 0) {
                src = g_xh[xsel] + (size_t)(tok0 + r)*512 + c*64 + u*8;
            } else {
                int mat = (c >> 3) ^ 2;     // k-segs: kI,kM,qI,qM -> mats 2,3,0,1
                src = g_ph[mat] + (size_t)(tok0 + r)*512 + (c & 7)*64 + u*8;
            }
            cp16(abase + r*128 + ((u ^ (r & 7)) << 4), src);
        }
        // B: 128 n-rows x 64 halves
        #pragma unroll
        for (int it = 0; it < 4; it++) {
            int v = it*256 + tid;
            int r = v >> 3, u = v & 7;
            const __half* src;
            if (MODE == 0) {
                src = g_Wth[which] + (size_t)(n0 + r)*512 + c*64 + u*8;
            } else {
                src = g_Wch[batch] + (size_t)(n0 + r)*2048 + c*64 + u*8;
            }
            cp16(bbase + r*128 + ((u ^ (r & 7)) << 4), src);
        }
        cp_commit();
    };

    float acc[2][8][4];
    #pragma unroll
    for (int mt = 0; mt < 2; mt++)
        #pragma unroll
        for (int nt = 0; nt < 8; nt++)
            #pragma unroll
            for (int e = 0; e < 4; e++) acc[mt][nt][e] = 0.f;

    const int wm = wid >> 1, wn = wid & 1;      // warps 4x2 -> 32m x 64n per warp
    const int mwb = wm * 32, nwb = wn * 64;

    issue(0, 0);
    issue(1, 1);

    int buf = 0;
    for (int c = 0; c < NC; c++) {
        if (c < NC - 1) cp_wait1(); else cp_wait0();
        __syncthreads();
        // overwrite the buffer consumed at chunk c-1 (barrier above proves all
        // warps are done with it)
        if (c + 2 < NC) {
            int nb = buf + 2; if (nb >= 3) nb -= 3;
            issue(c + 2, nb);
        }
        uint32_t abase = sb + buf*BUFSZ;
        uint32_t bbase = abase + 16384;

        #pragma unroll
        for (int k16 = 0; k16 < 4; k16++) {
            uint32_t ah[2][4], bh[4][4];
            #pragma unroll
            for (int mt = 0; mt < 2; mt++) {
                int row = mwb + mt*16 + (lane & 15);
                int kb  = k16*2 + (lane >> 4);
                ldsm4(ah[mt], abase + row*128 + ((kb ^ (row & 7)) << 4));
            }
            #pragma unroll
            for (int bt = 0; bt < 4; bt++) {
                int row = nwb + bt*16 + ((lane >> 4) << 3) + (lane & 7);
                int kb  = k16*2 + ((lane >> 3) & 1);
                ldsm4(bh[bt], bbase + row*128 + ((kb ^ (row & 7)) << 4));
            }
            #pragma unroll
            for (int mt = 0; mt < 2; mt++)
                #pragma unroll
                for (int nt = 0; nt < 8; nt++) {
                    int bt = nt >> 1, s = (nt & 1) * 2;
                    mma_f16(acc[mt][nt], ah[mt], bh[bt][s], bh[bt][s+1]);
                }
        }
        if (++buf >= 3) buf = 0;
    }

    // ---- epilogue ----
    #pragma unroll
    for (int mt = 0; mt < 2; mt++) {
        int row = tok0 + mwb + mt*16 + (lane >> 2);
        #pragma unroll
        for (int nt = 0; nt < 8; nt++) {
            int col = n0 + nwb + nt*8 + 2*(lane & 3);
            float b0 = sbias[col - n0], b1 = sbias[col - n0 + 1];
            if (MODE == 0) {
                __half* o = g_raw16[which];
                *(__half2*)(o + (size_t)row*512 + col) =
                    __floats2half2_rn(acc[mt][nt][0] + b0, acc[mt][nt][1] + b1);
                *(__half2*)(o + (size_t)(row+8)*512 + col) =
                    __floats2half2_rn(acc[mt][nt][2] + b0, acc[mt][nt][3] + b1);
            } else {
                *(float2*)(outp + (size_t)row*256 + col) =
                    make_float2(acc[mt][nt][0] + b0, acc[mt][nt][1] + b1);
                *(float2*)(outp + (size_t)(row+8)*256 + col) =
                    make_float2(acc[mt][nt][2] + b0, acc[mt][nt][3] + b1);
            }
        }
    }
}

// ---------------- x -> fp16 ----------------
__global__ void xconv_kernel(const float* __restrict__ xI, const float* __restrict__ xM)
{
    const int im = blockIdx.y;
    const float* x = im ? xM : xI;
    size_t off = ((size_t)blockIdx.x*256 + threadIdx.x) * 8;
    float4 f0 = *(const float4*)(x + off);
    float4 f1 = *(const float4*)(x + off + 4);
    __half h[8];
    h[0]=__float2half(f0.x); h[1]=__float2half(f0.y);
    h[2]=__float2half(f0.z); h[3]=__float2half(f0.w);
    h[4]=__float2half(f1.x); h[5]=__float2half(f1.y);
    h[6]=__float2half(f1.z); h[7]=__float2half(f1.w);
    *(uint4*)(&g_xh[im][off]) = *(uint4*)h;
}

// ---------------- normalize (dense-coalesced, high-occ): L2 norm + planes + Gu/s2 --
// grid (TOK/32, 4); 256 threads = 8 warps x 4 tokens
// lane i owns halves [i*8, i*8+8) and [256+i*8, 256+i*8+8) of each token row
__global__ void __launch_bounds__(256, 4) norm_kernel(
    const float* __restrict__ wgI, const float* __restrict__ wgM)
{
    const int which = blockIdx.y;
    const int tok0 = blockIdx.x * 32;
    const int b = tok0 >> 12;
    const bool isq = (which < 2);
    const __half* raw = g_raw16[which];
    __half* oh = g_ph[which];

    __shared__ float sGu[513];
    __shared__ float swg[512];
    const int warp = threadIdx.x >> 5, lane = threadIdx.x & 31;
    const int c0 = lane*8, c1 = 256 + lane*8;

    if (isq) {
        const float* wg = which ? wgM : wgI;
        swg[threadIdx.x]       = __ldg(&wg[threadIdx.x]);
        swg[threadIdx.x + 256] = __ldg(&wg[threadIdx.x + 256]);
        for (int c = threadIdx.x; c < 513; c += 256) sGu[c] = 0.f;
        __syncthreads();
    }

    float gu[16];
    #pragma unroll
    for (int j = 0; j < 16; j++) gu[j] = 0.f;
    float s2 = 0.f;

    #pragma unroll
    for (int i = 0; i < 4; i++) {
        const int t = tok0 + warp*4 + i;
        const size_t rowb = (size_t)t*512;
        uint4 d0 = *(const uint4*)(raw + rowb + c0);
        uint4 d1 = *(const uint4*)(raw + rowb + c1);
        __half2* hp0 = (__half2*)&d0;
        __half2* hp1 = (__half2*)&d1;
        float v[16];
        #pragma unroll
        for (int j = 0; j < 4; j++) {
            float2 f0 = __half22float2(hp0[j]);
            float2 f1 = __half22float2(hp1[j]);
            v[j*2]   = f0.x; v[j*2+1]   = f0.y;
            v[8+j*2] = f1.x; v[8+j*2+1] = f1.y;
        }
        float ss = 0.f;
        #pragma unroll
        for (int j = 0; j < 16; j++) ss += v[j]*v[j];
        #pragma unroll
        for (int o = 16; o; o >>= 1) ss += __shfl_xor_sync(0xFFFFFFFFu, ss, o);
        const float inv = 1.f / fmaxf(sqrtf(ss), 1e-12f);
        #pragma unroll
        for (int j = 0; j < 16; j++) v[j] *= inv;

        uint4 w0, w1; __half2 h;
        #pragma unroll
        for (int j = 0; j < 4; j++) {
            h = __floats2half2_rn(v[j*2],   v[j*2+1]);   ((uint32_t*)&w0)[j] = *(uint32_t*)&h;
            h = __floats2half2_rn(v[8+j*2], v[8+j*2+1]); ((uint32_t*)&w1)[j] = *(uint32_t*)&h;
        }
        *(uint4*)(oh + rowb + c0) = w0;
        *(uint4*)(oh + rowb + c1) = w1;

        if (isq) {
            float sp = 0.f;
            #pragma unroll
            for (int j = 0; j < 8; j++) {
                sp += v[j]   * swg[c0 + j];
                sp += v[8+j] * swg[c1 + j];
            }
            #pragma unroll
            for (int o = 16; o; o >>= 1) sp += __shfl_xor_sync(0xFFFFFFFFu, sp, o);
            #pragma unroll
            for (int j = 0; j < 16; j++) gu[j] += sp * v[j];
            s2 += sp * sp;
        }
    }
    if (isq) {
        #pragma unroll
        for (int j = 0; j < 8; j++) {
            atomicAdd(&sGu[c0 + j], gu[j]);
            atomicAdd(&sGu[c1 + j], gu[8+j]);
        }
        if (lane == 0) atomicAdd(&sGu[512], s2);
        __syncthreads();
        float* accG = g_acc + ((size_t)b*2 + which)*513;
        for (int c = threadIdx.x; c < 513; c += 256) atomicAdd(&accG[c], sGu[c]);
    }
}

// ---------------- setup: W^T fp16, f_w^T, zero acc, cvec ----------------
__global__ void setup_kernel(const float* __restrict__ wqI, const float* __restrict__ wqM,
                             const float* __restrict__ wkI, const float* __restrict__ wkM,
                             const float* __restrict__ fw,
                             const float* __restrict__ b1, const float* __restrict__ b2,
                             const float* __restrict__ b3, const float* __restrict__ b4,
                             const float* __restrict__ fb)
{
    if (blockIdx.x >= 4642) {
        // cvec: one column per block
        int c = blockIdx.x - 4642, t = threadIdx.x;
        float p = 0.f;
        for (int e = t; e < DD; e += 256)
            p += (b1[e] + b2[e] + b3[e] + b4[e]) * fw[(size_t)e*TD + c];
        #pragma unroll
        for (int o = 16; o; o >>= 1) p += __shfl_xor_sync(0xFFFFFFFFu, p, o);
        __shared__ float sp[8];
        if ((t & 31) == 0) sp[t >> 5] = p;
        __syncthreads();
        if (t == 0) {
            float s = fb[c];
            #pragma unroll
            for (int w = 0; w < 8; w++) s += sp[w];
            g_cvec[c] = s;
        }
        return;
    }
    int idx = blockIdx.x*256 + threadIdx.x;
    if (idx < 4*DD*DD) {
        int m = idx >> 18, r = idx & (DD*DD - 1);
        int n = r >> 9, k = r & 511;
        const float* W = (m==0)?wqI:(m==1)?wqM:(m==2)?wkI:wkM;
        g_Wth[m][r] = __float2half(W[(size_t)k*DD + n]);
    } else if ((idx -= 4*DD*DD) < TD*DD) {
        int n = idx >> 9, e = idx & 511;
        g_fwT[idx] = fw[(size_t)e*TD + n];
    } else if ((idx -= TD*DD) < BB*2*513) {
        g_acc[idx] = 0.f;
    }
}

// ---------------- PFt = (p_i @ f_w)^T  (parallel: 256 CTAs) ----------------
// grid (16, 4, 4): x = row tile (32 rows of p), y = matrix, z = col tile (64 n)
__global__ void __launch_bounds__(256) pf_kernel(
    const float* __restrict__ p1, const float* __restrict__ p2,
    const float* __restrict__ p3, const float* __restrict__ p4,
    const float* __restrict__ fw)
{
    const float* P[4] = {p1, p2, p3, p4};
    const float* p = P[blockIdx.y];
    float* out = g_PFt[blockIdx.y];
    const int r0 = blockIdx.x * 32;
    const int n0 = blockIdx.z * 64;

    __shared__ float sP[32][36];   // p rows tile, padded
    __shared__ float sF[32][64];   // fw tile
    const int warp = threadIdx.x >> 5, lane = threadIdx.x & 31;

    float acc[4][2];
    #pragma unroll
    for (int i = 0; i < 4; i++) { acc[i][0] = 0.f; acc[i][1] = 0.f; }

    for (int e0 = 0; e0 < DD; e0 += 32) {
        {
            int r = threadIdx.x >> 3, e4 = threadIdx.x & 7;
            *(float4*)&sP[r][e4*4] = *(const float4*)(p + (size_t)(r0 + r)*DD + e0 + e4*4);
        }
        #pragma unroll
        for (int it = 0; it < 2; it++) {
            int v = threadIdx.x + it*256;
            int e = v >> 4, f4 = v & 15;
            *(float4*)&sF[e][f4*4] = *(const float4*)(fw + (size_t)(e0 + e)*TD + n0 + f4*4);
        }
        __syncthreads();
        #pragma unroll
        for (int kk = 0; kk < 32; kk++) {
            float w0 = sF[kk][lane], w1 = sF[kk][lane + 32];
            #pragma unroll
            for (int i = 0; i < 4; i++) {
                float a = sP[4*warp + i][kk];
                acc[i][0] += a * w0;
                acc[i][1] += a * w1;
            }
        }
        __syncthreads();
    }
    #pragma unroll
    for (int i = 0; i < 4; i++) {
        out[(size_t)(n0 + lane)*DD      + r0 + 4*warp + i] = acc[i][0];
        out[(size_t)(n0 + lane + 32)*DD + r0 + 4*warp + i] = acc[i][1];
    }
}

// ---------------- combined weights Wc^T fp16 ----------------
// K segs (2048): [0,512)=kI, [512,1024)=kM, [1024,1536)=qI (f_w), [1536,2048)=qM (f_w)
__global__ void combine_kernel()
{
    int n = blockIdx.x, b = blockIdx.y, t = threadIdx.x;
    const float* acc = g_acc + (size_t)b*2*513;
    float nI = fmaxf(SCALE_F * sqrtf(acc[512]),       1e-12f);
    float nM = fmaxf(SCALE_F * sqrtf(acc[513 + 512]), 1e-12f);
    for (int k = t; k < 2048; k += 256) {
        float v;
        if (k < 1024) {
            int kk = k & 511;
            float GI = SCALE_F * acc[kk] / nI;
            float GM = SCALE_F * acc[513 + kk] / nM;
            if (k < 512) v = GI*g_PFt[0][(size_t)n*DD+kk] + GM*g_PFt[3][(size_t)n*DD+kk];
            else         v = GI*g_PFt[1][(size_t)n*DD+kk] + GM*g_PFt[2][(size_t)n*DD+kk];
        } else {
            v = g_fwT[(size_t)n*DD + (k & 511)];
        }
        g_Wch[b][(size_t)n*2048 + k] = __float2half(v);
    }
}

// ---------------- launch ----------------
extern "C" void kernel_launch(void* const* d_in, const int* in_sizes, int n_in,
                              void* d_out, int out_size)
{
    const float* xI  = (const float*)d_in[0];
    const float* xM  = (const float*)d_in[1];
    const float* wqI = (const float*)d_in[2];
    const float* bqI = (const float*)d_in[3];
    const float* wkI = (const float*)d_in[4];
    const float* bkI = (const float*)d_in[5];
    const float* wqM = (const float*)d_in[6];
    const float* bqM = (const float*)d_in[7];
    const float* wkM = (const float*)d_in[8];
    const float* bkM = (const float*)d_in[9];
    const float* wgI = (const float*)d_in[10];
    const float* wgM = (const float*)d_in[11];
    const float* p1w = (const float*)d_in[12];
    const float* p1b = (const float*)d_in[13];
    const float* p2w = (const float*)d_in[14];
    const float* p2b = (const float*)d_in[15];
    const float* p3w = (const float*)d_in[16];
    const float* p3b = (const float*)d_in[17];
    const float* p4w = (const float*)d_in[18];
    const float* p4b = (const float*)d_in[19];
    const float* fw  = (const float*)d_in[20];
    const float* fb  = (const float*)d_in[21];
    float* out = (float*)d_out;

    cudaFuncSetAttribute(mma_gemm<0>, cudaFuncAttributeMaxDynamicSharedMemorySize, SMEM_TOTAL);
    cudaFuncSetAttribute(mma_gemm<1>, cudaFuncAttributeMaxDynamicSharedMemorySize, SMEM_TOTAL);

    setup_kernel<<<4642 + TD, 256>>>(wqI, wqM, wkI, wkM, fw, p1b, p2b, p3b, p4b, fb);
    xconv_kernel<<<dim3(TOK*DD/(256*8), 2), 256>>>(xI, xM);
    mma_gemm<0><<<4096, 256, SMEM_TOTAL>>>(bqI, bqM, bkI, bkM, nullptr);
    norm_kernel<<<dim3(TOK/32, 4), 256>>>(wgI, wgM);
    pf_kernel<<<dim3(16, 4, 4), 256>>>(p1w, p2w, p3w, p4w, fw);
    combine_kernel<<<dim3(TD, BB), 256>>>();
    mma_gemm<1><<<512, 256, SMEM_TOTAL>>>(bqI, bqM, bkI, bkM, out);
}

// round 15
// speedup vs baseline: 1.0444x; 1.0444x over previous
#include <cuda_runtime.h>
#include <cuda_fp16.h>
#include <math.h>
#include <stdint.h>

#define BB 8
#define NN 4096
#define DD 512
#define TD 256
#define TOK (BB*NN)
#define SCALE_F 0.0625f

// ---------------- static scratch ----------------
__device__ __align__(16) __half g_xh[2][(size_t)TOK*DD];     // x fp16 (I, M)
__device__ __align__(16) __half g_raw16[4][(size_t)TOK*DD];  // proj out + bias, fp16
__device__ __align__(16) __half g_ph[4][(size_t)TOK*DD];     // normalized q/k fp16 [qI,qM,kI,kM]
__device__ __align__(16) __half g_Wth[4][DD*DD];             // W^T fp16 [mat][n][k]
__device__ __align__(16) __half g_Wch[BB][TD*2048];          // combined W^T fp16 [b][n][k]
__device__ float g_fwT[TD*DD];                               // f_w^T [n][e]
__device__ float g_PFt[4][TD*DD];                            // (p_i@f_w)^T [n][k]
__device__ float g_acc[BB*2*513];
__device__ float g_cvec[TD];

// ---------------- helpers ----------------
__device__ __forceinline__ uint32_t smem_u32(const void* p) {
    uint32_t a;
    asm("{ .reg .u64 t; cvta.to.shared.u64 t, %1; cvt.u32.u64 %0, t; }" : "=r"(a) : "l"(p));
    return a;
}
__device__ __forceinline__ void cp16(uint32_t s, const void* g) {
    asm volatile("cp.async.cg.shared.global [%0], [%1], 16;" :: "r"(s), "l"(g));
}
__device__ __forceinline__ void cp_commit() { asm volatile("cp.async.commit_group;"); }
__device__ __forceinline__ void cp_wait1()  { asm volatile("cp.async.wait_group 1;"); }
__device__ __forceinline__ void cp_wait0()  { asm volatile("cp.async.wait_group 0;"); }
__device__ __forceinline__ void ldsm4(uint32_t* r, uint32_t addr) {
    asm volatile("ldmatrix.sync.aligned.m8n8.x4.shared.b16 {%0,%1,%2,%3}, [%4];"
        : "=r"(r[0]), "=r"(r[1]), "=r"(r[2]), "=r"(r[3]) : "r"(addr));
}
__device__ __forceinline__ void mma_f16(float* c, const uint32_t* a, uint32_t b0, uint32_t b1) {
    asm volatile("mma.sync.aligned.m16n8k16.row.col.f32.f16.f16.f32 "
        "{%0,%1,%2,%3}, {%4,%5,%6,%7}, {%8,%9}, {%0,%1,%2,%3};"
        : "+f"(c[0]), "+f"(c[1]), "+f"(c[2]), "+f"(c[3])
        : "r"(a[0]), "r"(a[1]), "r"(a[2]), "r"(a[3]), "r"(b0), "r"(b1));
}

// SMEM per buffer: A 16KB + B 16KB = 32KB; ring of 3 = 96KB
#define BUFSZ 32768
#define SMEM_TOTAL 98304

// ---------------- MMA GEMM (MODE 0 = proj -> raw16 (+bias); MODE 1 = final -> out) ----
// MODE 0 grid: 4096 flat; bx&3=which, (bx>>2)&3=ntile, bx>>4=tokblk (A sharers adjacent)
// MODE 1 grid: 512 flat;  bx&1=ntile, bx>>1=tokblk
template<int MODE>
__global__ void __launch_bounds__(256) mma_gemm(
    const float* __restrict__ bqI, const float* __restrict__ bqM,
    const float* __restrict__ bkI, const float* __restrict__ bkM,
    float* __restrict__ outp)
{
    extern __shared__ char smem[];
    const uint32_t sb = smem_u32(smem);
    __shared__ float sbias[128];

    const int tid = threadIdx.x, wid = tid >> 5, lane = tid & 31;
    const int bx = blockIdx.x;
    const int which = (MODE == 0) ? (bx & 3) : 0;
    const int n0    = (MODE == 0) ? (((bx >> 2) & 3) * 128) : ((bx & 1) * 128);
    const int tok0  = (MODE == 0) ? ((bx >> 4) * 128) : ((bx >> 1) * 128);
    const int batch = tok0 >> 12;
    const int NC = (MODE == 0) ? 8 : 32;

    if (MODE == 0) {
        const float* bias = (which==0)?bqI:(which==1)?bqM:(which==2)?bkI:bkM;
        if (tid < 128) sbias[tid] = bias[n0 + tid];
    } else {
        if (tid < 128) sbias[tid] = g_cvec[n0 + tid];
    }

    const int xsel = which & 1;

    // ---- issue chunk c (Kc=64) into ring buffer via cp.async ----
    auto issue = [&](int c, int buf) {
        uint32_t abase = sb + buf*BUFSZ;
        uint32_t bbase = abase + 16384;
        // A: 128 rows x 64 halves (8 x 16B per row)
        #pragma unroll
        for (int it = 0; it < 4; it++) {
            int v = it*256 + tid;
            int r = v >> 3, u = v & 7;
            const __half* src;
            if (MODE == 0) {
                src = g_xh[xsel] + (size_t)(tok0 + r)*512 + c*64 + u*8;
            } else {
                int mat = (c >> 3) ^ 2;     // k-segs: kI,kM,qI,qM -> mats 2,3,0,1
                src = g_ph[mat] + (size_t)(tok0 + r)*512 + (c & 7)*64 + u*8;
            }
            cp16(abase + r*128 + ((u ^ (r & 7)) << 4), src);
        }
        // B: 128 n-rows x 64 halves
        #pragma unroll
        for (int it = 0; it < 4; it++) {
            int v = it*256 + tid;
            int r = v >> 3, u = v & 7;
            const __half* src;
            if (MODE == 0) {
                src = g_Wth[which] + (size_t)(n0 + r)*512 + c*64 + u*8;
            } else {
                src = g_Wch[batch] + (size_t)(n0 + r)*2048 + c*64 + u*8;
            }
            cp16(bbase + r*128 + ((u ^ (r & 7)) << 4), src);
        }
        cp_commit();
    };

    float acc[2][8][4];
    #pragma unroll
    for (int mt = 0; mt < 2; mt++)
        #pragma unroll
        for (int nt = 0; nt < 8; nt++)
            #pragma unroll
            for (int e = 0; e < 4; e++) acc[mt][nt][e] = 0.f;

    const int wm = wid >> 1, wn = wid & 1;      // warps 4x2 -> 32m x 64n per warp
    const int mwb = wm * 32, nwb = wn * 64;

    issue(0, 0);
    issue(1, 1);

    int buf = 0;
    for (int c = 0; c < NC; c++) {
        if (c < NC - 1) cp_wait1(); else cp_wait0();
        __syncthreads();
        // overwrite the buffer consumed at chunk c-1 (barrier above proves all
        // warps are done with it)
        if (c + 2 < NC) {
            int nb = buf + 2; if (nb >= 3) nb -= 3;
            issue(c + 2, nb);
        }
        uint32_t abase = sb + buf*BUFSZ;
        uint32_t bbase = abase + 16384;

        #pragma unroll
        for (int k16 = 0; k16 < 4; k16++) {
            uint32_t ah[2][4], bh[4][4];
            #pragma unroll
            for (int mt = 0; mt < 2; mt++) {
                int row = mwb + mt*16 + (lane & 15);
                int kb  = k16*2 + (lane >> 4);
                ldsm4(ah[mt], abase + row*128 + ((kb ^ (row & 7)) << 4));
            }
            #pragma unroll
            for (int bt = 0; bt < 4; bt++) {
                int row = nwb + bt*16 + ((lane >> 4) << 3) + (lane & 7);
                int kb  = k16*2 + ((lane >> 3) & 1);
                ldsm4(bh[bt], bbase + row*128 + ((kb ^ (row & 7)) << 4));
            }
            #pragma unroll
            for (int mt = 0; mt < 2; mt++)
                #pragma unroll
                for (int nt = 0; nt < 8; nt++) {
                    int bt = nt >> 1, s = (nt & 1) * 2;
                    mma_f16(acc[mt][nt], ah[mt], bh[bt][s], bh[bt][s+1]);
                }
        }
        if (++buf >= 3) buf = 0;
    }

    // ---- epilogue ----
    #pragma unroll
    for (int mt = 0; mt < 2; mt++) {
        int row = tok0 + mwb + mt*16 + (lane >> 2);
        #pragma unroll
        for (int nt = 0; nt < 8; nt++) {
            int col = n0 + nwb + nt*8 + 2*(lane & 3);
            float b0 = sbias[col - n0], b1 = sbias[col - n0 + 1];
            if (MODE == 0) {
                __half* o = g_raw16[which];
                *(__half2*)(o + (size_t)row*512 + col) =
                    __floats2half2_rn(acc[mt][nt][0] + b0, acc[mt][nt][1] + b1);
                *(__half2*)(o + (size_t)(row+8)*512 + col) =
                    __floats2half2_rn(acc[mt][nt][2] + b0, acc[mt][nt][3] + b1);
            } else {
                *(float2*)(outp + (size_t)row*256 + col) =
                    make_float2(acc[mt][nt][0] + b0, acc[mt][nt][1] + b1);
                *(float2*)(outp + (size_t)(row+8)*256 + col) =
                    make_float2(acc[mt][nt][2] + b0, acc[mt][nt][3] + b1);
            }
        }
    }
}

// ---------------- x -> fp16 ----------------
__global__ void xconv_kernel(const float* __restrict__ xI, const float* __restrict__ xM)
{
    const int im = blockIdx.y;
    const float* x = im ? xM : xI;
    size_t off = ((size_t)blockIdx.x*256 + threadIdx.x) * 8;
    float4 f0 = *(const float4*)(x + off);
    float4 f1 = *(const float4*)(x + off + 4);
    __half h[8];
    h[0]=__float2half(f0.x); h[1]=__float2half(f0.y);
    h[2]=__float2half(f0.z); h[3]=__float2half(f0.w);
    h[4]=__float2half(f1.x); h[5]=__float2half(f1.y);
    h[6]=__float2half(f1.z); h[7]=__float2half(f1.w);
    *(uint4*)(&g_xh[im][off]) = *(uint4*)h;
}

// ---------------- normalize: coalesced uint4 + 4-token ILP shuffle chains --------
// grid (TOK/32, 4); 256 threads = 8 warps x 4 tokens
// lane i owns halves [i*8, i*8+8) and [256+i*8, 256+i*8+8) of each token row
__global__ void __launch_bounds__(256) norm_kernel(
    const float* __restrict__ wgI, const float* __restrict__ wgM)
{
    const int which = blockIdx.y;
    const int tok0 = blockIdx.x * 32;
    const int b = tok0 >> 12;
    const bool isq = (which < 2);
    const __half* raw = g_raw16[which];
    __half* oh = g_ph[which];

    __shared__ float sGu[513];
    const int warp = threadIdx.x >> 5, lane = threadIdx.x & 31;
    const int c0 = lane*8, c1 = 256 + lane*8;

    float wgv[16];
    if (isq) {
        const float* wg = which ? wgM : wgI;
        #pragma unroll
        for (int j = 0; j < 8; j++) {
            wgv[j]   = __ldg(&wg[c0 + j]);
            wgv[8+j] = __ldg(&wg[c1 + j]);
        }
        for (int c = threadIdx.x; c < 513; c += 256) sGu[c] = 0.f;
        __syncthreads();
    }

    // ---- load all 4 tokens (coalesced uint4) ----
    float v[4][16];
    #pragma unroll
    for (int i = 0; i < 4; i++) {
        const size_t rowb = (size_t)(tok0 + warp*4 + i)*512;
        uint4 d0 = *(const uint4*)(raw + rowb + c0);
        uint4 d1 = *(const uint4*)(raw + rowb + c1);
        __half2* hp0 = (__half2*)&d0;
        __half2* hp1 = (__half2*)&d1;
        #pragma unroll
        for (int j = 0; j < 4; j++) {
            float2 f0 = __half22float2(hp0[j]);
            float2 f1 = __half22float2(hp1[j]);
            v[i][j*2]   = f0.x; v[i][j*2+1]   = f0.y;
            v[i][8+j*2] = f1.x; v[i][8+j*2+1] = f1.y;
        }
    }

    // ---- 4 interleaved sum-of-squares reductions ----
    float ss[4];
    #pragma unroll
    for (int i = 0; i < 4; i++) {
        float t = 0.f;
        #pragma unroll
        for (int j = 0; j < 16; j++) t += v[i][j]*v[i][j];
        ss[i] = t;
    }
    #pragma unroll
    for (int o = 16; o; o >>= 1) {
        #pragma unroll
        for (int i = 0; i < 4; i++)
            ss[i] += __shfl_xor_sync(0xFFFFFFFFu, ss[i], o);
    }
    #pragma unroll
    for (int i = 0; i < 4; i++) {
        const float inv = 1.f / fmaxf(sqrtf(ss[i]), 1e-12f);
        #pragma unroll
        for (int j = 0; j < 16; j++) v[i][j] *= inv;
    }

    // ---- store normalized (coalesced uint4) ----
    #pragma unroll
    for (int i = 0; i < 4; i++) {
        const size_t rowb = (size_t)(tok0 + warp*4 + i)*512;
        uint4 w0, w1; __half2 h;
        #pragma unroll
        for (int j = 0; j < 4; j++) {
            h = __floats2half2_rn(v[i][j*2],   v[i][j*2+1]);   ((uint32_t*)&w0)[j] = *(uint32_t*)&h;
            h = __floats2half2_rn(v[i][8+j*2], v[i][8+j*2+1]); ((uint32_t*)&w1)[j] = *(uint32_t*)&h;
        }
        *(uint4*)(oh + rowb + c0) = w0;
        *(uint4*)(oh + rowb + c1) = w1;
    }

    // ---- q path: s = q.wg (4 interleaved chains), Gu, s2 ----
    if (isq) {
        float sp[4];
        #pragma unroll
        for (int i = 0; i < 4; i++) {
            float t = 0.f;
            #pragma unroll
            for (int j = 0; j < 16; j++) t += v[i][j]*wgv[j];
            sp[i] = t;
        }
        #pragma unroll
        for (int o = 16; o; o >>= 1) {
            #pragma unroll
            for (int i = 0; i < 4; i++)
                sp[i] += __shfl_xor_sync(0xFFFFFFFFu, sp[i], o);
        }
        #pragma unroll
        for (int j = 0; j < 8; j++) {
            float g0 = sp[0]*v[0][j]   + sp[1]*v[1][j]   + sp[2]*v[2][j]   + sp[3]*v[3][j];
            float g1 = sp[0]*v[0][8+j] + sp[1]*v[1][8+j] + sp[2]*v[2][8+j] + sp[3]*v[3][8+j];
            atomicAdd(&sGu[c0 + j], g0);
            atomicAdd(&sGu[c1 + j], g1);
        }
        if (lane == 0)
            atomicAdd(&sGu[512], sp[0]*sp[0] + sp[1]*sp[1] + sp[2]*sp[2] + sp[3]*sp[3]);
        __syncthreads();
        float* accG = g_acc + ((size_t)b*2 + which)*513;
        for (int c = threadIdx.x; c < 513; c += 256) atomicAdd(&accG[c], sGu[c]);
    }
}

// ---------------- setup: W^T fp16, f_w^T, zero acc, cvec ----------------
__global__ void setup_kernel(const float* __restrict__ wqI, const float* __restrict__ wqM,
                             const float* __restrict__ wkI, const float* __restrict__ wkM,
                             const float* __restrict__ fw,
                             const float* __restrict__ b1, const float* __restrict__ b2,
                             const float* __restrict__ b3, const float* __restrict__ b4,
                             const float* __restrict__ fb)
{
    if (blockIdx.x >= 4642) {
        // cvec: one column per block
        int c = blockIdx.x - 4642, t = threadIdx.x;
        float p = 0.f;
        for (int e = t; e < DD; e += 256)
            p += (b1[e] + b2[e] + b3[e] + b4[e]) * fw[(size_t)e*TD + c];
        #pragma unroll
        for (int o = 16; o; o >>= 1) p += __shfl_xor_sync(0xFFFFFFFFu, p, o);
        __shared__ float sp[8];
        if ((t & 31) == 0) sp[t >> 5] = p;
        __syncthreads();
        if (t == 0) {
            float s = fb[c];
            #pragma unroll
            for (int w = 0; w < 8; w++) s += sp[w];
            g_cvec[c] = s;
        }
        return;
    }
    int idx = blockIdx.x*256 + threadIdx.x;
    if (idx < 4*DD*DD) {
        int m = idx >> 18, r = idx & (DD*DD - 1);
        int n = r >> 9, k = r & 511;
        const float* W = (m==0)?wqI:(m==1)?wqM:(m==2)?wkI:wkM;
        g_Wth[m][r] = __float2half(W[(size_t)k*DD + n]);
    } else if ((idx -= 4*DD*DD) < TD*DD) {
        int n = idx >> 9, e = idx & 511;
        g_fwT[idx] = fw[(size_t)e*TD + n];
    } else if ((idx -= TD*DD) < BB*2*513) {
        g_acc[idx] = 0.f;
    }
}

// ---------------- PFt = (p_i @ f_w)^T  (parallel: 256 CTAs) ----------------
// grid (16, 4, 4): x = row tile (32 rows of p), y = matrix, z = col tile (64 n)
__global__ void __launch_bounds__(256) pf_kernel(
    const float* __restrict__ p1, const float* __restrict__ p2,
    const float* __restrict__ p3, const float* __restrict__ p4,
    const float* __restrict__ fw)
{
    const float* P[4] = {p1, p2, p3, p4};
    const float* p = P[blockIdx.y];
    float* out = g_PFt[blockIdx.y];
    const int r0 = blockIdx.x * 32;
    const int n0 = blockIdx.z * 64;

    __shared__ float sP[32][36];   // p rows tile, padded
    __shared__ float sF[32][64];   // fw tile
    const int warp = threadIdx.x >> 5, lane = threadIdx.x & 31;

    float acc[4][2];
    #pragma unroll
    for (int i = 0; i < 4; i++) { acc[i][0] = 0.f; acc[i][1] = 0.f; }

    for (int e0 = 0; e0 < DD; e0 += 32) {
        {
            int r = threadIdx.x >> 3, e4 = threadIdx.x & 7;
            *(float4*)&sP[r][e4*4] = *(const float4*)(p + (size_t)(r0 + r)*DD + e0 + e4*4);
        }
        #pragma unroll
        for (int it = 0; it < 2; it++) {
            int v = threadIdx.x + it*256;
            int e = v >> 4, f4 = v & 15;
            *(float4*)&sF[e][f4*4] = *(const float4*)(fw + (size_t)(e0 + e)*TD + n0 + f4*4);
        }
        __syncthreads();
        #pragma unroll
        for (int kk = 0; kk < 32; kk++) {
            float w0 = sF[kk][lane], w1 = sF[kk][lane + 32];
            #pragma unroll
            for (int i = 0; i < 4; i++) {
                float a = sP[4*warp + i][kk];
                acc[i][0] += a * w0;
                acc[i][1] += a * w1;
            }
        }
        __syncthreads();
    }
    #pragma unroll
    for (int i = 0; i < 4; i++) {
        out[(size_t)(n0 + lane)*DD      + r0 + 4*warp + i] = acc[i][0];
        out[(size_t)(n0 + lane + 32)*DD + r0 + 4*warp + i] = acc[i][1];
    }
}

// ---------------- combined weights Wc^T fp16 ----------------
// K segs (2048): [0,512)=kI, [512,1024)=kM, [1024,1536)=qI (f_w), [1536,2048)=qM (f_w)
__global__ void combine_kernel()
{
    int n = blockIdx.x, b = blockIdx.y, t = threadIdx.x;
    const float* acc = g_acc + (size_t)b*2*513;
    float nI = fmaxf(SCALE_F * sqrtf(acc[512]),       1e-12f);
    float nM = fmaxf(SCALE_F * sqrtf(acc[513 + 512]), 1e-12f);
    for (int k = t; k < 2048; k += 256) {
        float v;
        if (k < 1024) {
            int kk = k & 511;
            float GI = SCALE_F * acc[kk] / nI;
            float GM = SCALE_F * acc[513 + kk] / nM;
            if (k < 512) v = GI*g_PFt[0][(size_t)n*DD+kk] + GM*g_PFt[3][(size_t)n*DD+kk];
            else         v = GI*g_PFt[1][(size_t)n*DD+kk] + GM*g_PFt[2][(size_t)n*DD+kk];
        } else {
            v = g_fwT[(size_t)n*DD + (k & 511)];
        }
        g_Wch[b][(size_t)n*2048 + k] = __float2half(v);
    }
}

// ---------------- launch ----------------
extern "C" void kernel_launch(void* const* d_in, const int* in_sizes, int n_in,
                              void* d_out, int out_size)
{
    const float* xI  = (const float*)d_in[0];
    const float* xM  = (const float*)d_in[1];
    const float* wqI = (const float*)d_in[2];
    const float* bqI = (const float*)d_in[3];
    const float* wkI = (const float*)d_in[4];
    const float* bkI = (const float*)d_in[5];
    const float* wqM = (const float*)d_in[6];
    const float* bqM = (const float*)d_in[7];
    const float* wkM = (const float*)d_in[8];
    const float* bkM = (const float*)d_in[9];
    const float* wgI = (const float*)d_in[10];
    const float* wgM = (const float*)d_in[11];
    const float* p1w = (const float*)d_in[12];
    const float* p1b = (const float*)d_in[13];
    const float* p2w = (const float*)d_in[14];
    const float* p2b = (const float*)d_in[15];
    const float* p3w = (const float*)d_in[16];
    const float* p3b = (const float*)d_in[17];
    const float* p4w = (const float*)d_in[18];
    const float* p4b = (const float*)d_in[19];
    const float* fw  = (const float*)d_in[20];
    const float* fb  = (const float*)d_in[21];
    float* out = (float*)d_out;

    cudaFuncSetAttribute(mma_gemm<0>, cudaFuncAttributeMaxDynamicSharedMemorySize, SMEM_TOTAL);
    cudaFuncSetAttribute(mma_gemm<1>, cudaFuncAttributeMaxDynamicSharedMemorySize, SMEM_TOTAL);

    setup_kernel<<<4642 + TD, 256>>>(wqI, wqM, wkI, wkM, fw, p1b, p2b, p3b, p4b, fb);
    xconv_kernel<<<dim3(TOK*DD/(256*8), 2), 256>>>(xI, xM);
    mma_gemm<0><<<4096, 256, SMEM_TOTAL>>>(bqI, bqM, bkI, bkM, nullptr);
    norm_kernel<<<dim3(TOK/32, 4), 256>>>(wgI, wgM);
    pf_kernel<<<dim3(16, 4, 4), 256>>>(p1w, p2w, p3w, p4w, fw);
    combine_kernel<<<dim3(TD, BB), 256>>>();
    mma_gemm<1><<<512, 256, SMEM_TOTAL>>>(bqI, bqM, bkI, bkM, out);
}

// round 16
// speedup vs baseline: 1.0661x; 1.0207x over previous
#include <cuda_runtime.h>
#include <cuda_fp16.h>
#include <math.h>
#include <stdint.h>

#define BB 8
#define NN 4096
#define DD 512
#define TD 256
#define TOK (BB*NN)
#define SCALE_F 0.0625f

// ---------------- static scratch ----------------
__device__ __align__(16) __half g_xh[2][(size_t)TOK*DD];     // x fp16 (I, M)
__device__ __align__(16) __half g_raw16[4][(size_t)TOK*DD];  // proj out + bias, fp16
__device__ __align__(16) __half g_ph[4][(size_t)TOK*DD];     // normalized q/k fp16 [qI,qM,kI,kM]
__device__ __align__(16) __half g_Wth[4][DD*DD];             // W^T fp16 [mat][n][k]
__device__ __align__(16) __half g_Wch[BB][TD*2048];          // combined W^T fp16 [b][n][k]
__device__ float g_fwT[TD*DD];                               // f_w^T [n][e]
__device__ float g_PFt[4][TD*DD];                            // (p_i@f_w)^T [n][k]
__device__ float g_acc[BB*2*513];
__device__ float g_cvec[TD];

// ---------------- helpers ----------------
__device__ __forceinline__ uint32_t smem_u32(const void* p) {
    uint32_t a;
    asm("{ .reg .u64 t; cvta.to.shared.u64 t, %1; cvt.u32.u64 %0, t; }" : "=r"(a) : "l"(p));
    return a;
}
__device__ __forceinline__ void cp16(uint32_t s, const void* g) {
    asm volatile("cp.async.cg.shared.global [%0], [%1], 16;" :: "r"(s), "l"(g));
}
__device__ __forceinline__ void cp_commit() { asm volatile("cp.async.commit_group;"); }
__device__ __forceinline__ void cp_wait1()  { asm volatile("cp.async.wait_group 1;"); }
__device__ __forceinline__ void cp_wait0()  { asm volatile("cp.async.wait_group 0;"); }
__device__ __forceinline__ void ldsm4(uint32_t* r, uint32_t addr) {
    asm volatile("ldmatrix.sync.aligned.m8n8.x4.shared.b16 {%0,%1,%2,%3}, [%4];"
        : "=r"(r[0]), "=r"(r[1]), "=r"(r[2]), "=r"(r[3]) : "r"(addr));
}
__device__ __forceinline__ void mma_f16(float* c, const uint32_t* a, uint32_t b0, uint32_t b1) {
    asm volatile("mma.sync.aligned.m16n8k16.row.col.f32.f16.f16.f32 "
        "{%0,%1,%2,%3}, {%4,%5,%6,%7}, {%8,%9}, {%0,%1,%2,%3};"
        : "+f"(c[0]), "+f"(c[1]), "+f"(c[2]), "+f"(c[3])
        : "r"(a[0]), "r"(a[1]), "r"(a[2]), "r"(a[3]), "r"(b0), "r"(b1));
}

// SMEM per buffer: A 16KB + B 16KB = 32KB; ring of 3 = 96KB
#define BUFSZ 32768
#define SMEM_TOTAL 98304

// ---------------- MMA GEMM (MODE 0 = proj -> raw16 (+bias); MODE 1 = final -> out) ----
// MODE 0 grid: 4096 flat; bx&3=which, (bx>>2)&3=ntile, bx>>4=tokblk (A sharers adjacent)
// MODE 1 grid: 512 flat;  bx&1=ntile, bx>>1=tokblk
template<int MODE>
__global__ void __launch_bounds__(256) mma_gemm(
    const float* __restrict__ bqI, const float* __restrict__ bqM,
    const float* __restrict__ bkI, const float* __restrict__ bkM,
    float* __restrict__ outp)
{
    extern __shared__ char smem[];
    const uint32_t sb = smem_u32(smem);
    __shared__ float sbias[128];

    const int tid = threadIdx.x, wid = tid >> 5, lane = tid & 31;
    const int bx = blockIdx.x;
    const int which = (MODE == 0) ? (bx & 3) : 0;
    const int n0    = (MODE == 0) ? (((bx >> 2) & 3) * 128) : ((bx & 1) * 128);
    const int tok0  = (MODE == 0) ? ((bx >> 4) * 128) : ((bx >> 1) * 128);
    const int batch = tok0 >> 12;
    const int NC = (MODE == 0) ? 8 : 32;

    if (MODE == 0) {
        const float* bias = (which==0)?bqI:(which==1)?bqM:(which==2)?bkI:bkM;
        if (tid < 128) sbias[tid] = bias[n0 + tid];
    } else {
        if (tid < 128) sbias[tid] = g_cvec[n0 + tid];
    }

    const int xsel = which & 1;

    // ---- issue chunk c (Kc=64) into ring buffer via cp.async ----
    auto issue = [&](int c, int buf) {
        uint32_t abase = sb + buf*BUFSZ;
        uint32_t bbase = abase + 16384;
        // A: 128 rows x 64 halves (8 x 16B per row)
        #pragma unroll
        for (int it = 0; it < 4; it++) {
            int v = it*256 + tid;
            int r = v >> 3, u = v & 7;
            const __half* src;
            if (MODE == 0) {
                src = g_xh[xsel] + (size_t)(tok0 + r)*512 + c*64 + u*8;
            } else {
                int mat = (c >> 3) ^ 2;     // k-segs: kI,kM,qI,qM -> mats 2,3,0,1
                src = g_ph[mat] + (size_t)(tok0 + r)*512 + (c & 7)*64 + u*8;
            }
            cp16(abase + r*128 + ((u ^ (r & 7)) << 4), src);
        }
        // B: 128 n-rows x 64 halves
        #pragma unroll
        for (int it = 0; it < 4; it++) {
            int v = it*256 + tid;
            int r = v >> 3, u = v & 7;
            const __half* src;
            if (MODE == 0) {
                src = g_Wth[which] + (size_t)(n0 + r)*512 + c*64 + u*8;
            } else {
                src = g_Wch[batch] + (size_t)(n0 + r)*2048 + c*64 + u*8;
            }
            cp16(bbase + r*128 + ((u ^ (r & 7)) << 4), src);
        }
        cp_commit();
    };

    float acc[2][8][4];
    #pragma unroll
    for (int mt = 0; mt < 2; mt++)
        #pragma unroll
        for (int nt = 0; nt < 8; nt++)
            #pragma unroll
            for (int e = 0; e < 4; e++) acc[mt][nt][e] = 0.f;

    const int wm = wid >> 1, wn = wid & 1;      // warps 4x2 -> 32m x 64n per warp
    const int mwb = wm * 32, nwb = wn * 64;

    issue(0, 0);
    issue(1, 1);

    int buf = 0;
    for (int c = 0; c < NC; c++) {
        if (c < NC - 1) cp_wait1(); else cp_wait0();
        __syncthreads();
        // overwrite the buffer consumed at chunk c-1 (barrier above proves all
        // warps are done with it)
        if (c + 2 < NC) {
            int nb = buf + 2; if (nb >= 3) nb -= 3;
            issue(c + 2, nb);
        }
        uint32_t abase = sb + buf*BUFSZ;
        uint32_t bbase = abase + 16384;

        #pragma unroll
        for (int k16 = 0; k16 < 4; k16++) {
            uint32_t ah[2][4], bh[4][4];
            #pragma unroll
            for (int mt = 0; mt < 2; mt++) {
                int row = mwb + mt*16 + (lane & 15);
                int kb  = k16*2 + (lane >> 4);
                ldsm4(ah[mt], abase + row*128 + ((kb ^ (row & 7)) << 4));
            }
            #pragma unroll
            for (int bt = 0; bt < 4; bt++) {
                int row = nwb + bt*16 + ((lane >> 4) << 3) + (lane & 7);
                int kb  = k16*2 + ((lane >> 3) & 1);
                ldsm4(bh[bt], bbase + row*128 + ((kb ^ (row & 7)) << 4));
            }
            #pragma unroll
            for (int mt = 0; mt < 2; mt++)
                #pragma unroll
                for (int nt = 0; nt < 8; nt++) {
                    int bt = nt >> 1, s = (nt & 1) * 2;
                    mma_f16(acc[mt][nt], ah[mt], bh[bt][s], bh[bt][s+1]);
                }
        }
        if (++buf >= 3) buf = 0;
    }

    // ---- epilogue ----
    #pragma unroll
    for (int mt = 0; mt < 2; mt++) {
        int row = tok0 + mwb + mt*16 + (lane >> 2);
        #pragma unroll
        for (int nt = 0; nt < 8; nt++) {
            int col = n0 + nwb + nt*8 + 2*(lane & 3);
            float b0 = sbias[col - n0], b1 = sbias[col - n0 + 1];
            if (MODE == 0) {
                __half* o = g_raw16[which];
                *(__half2*)(o + (size_t)row*512 + col) =
                    __floats2half2_rn(acc[mt][nt][0] + b0, acc[mt][nt][1] + b1);
                *(__half2*)(o + (size_t)(row+8)*512 + col) =
                    __floats2half2_rn(acc[mt][nt][2] + b0, acc[mt][nt][3] + b1);
            } else {
                *(float2*)(outp + (size_t)row*256 + col) =
                    make_float2(acc[mt][nt][0] + b0, acc[mt][nt][1] + b1);
                *(float2*)(outp + (size_t)(row+8)*256 + col) =
                    make_float2(acc[mt][nt][2] + b0, acc[mt][nt][3] + b1);
            }
        }
    }
}

// ---------------- x -> fp16 ----------------
__global__ void xconv_kernel(const float* __restrict__ xI, const float* __restrict__ xM)
{
    const int im = blockIdx.y;
    const float* x = im ? xM : xI;
    size_t off = ((size_t)blockIdx.x*256 + threadIdx.x) * 8;
    float4 f0 = *(const float4*)(x + off);
    float4 f1 = *(const float4*)(x + off + 4);
    __half h[8];
    h[0]=__float2half(f0.x); h[1]=__float2half(f0.y);
    h[2]=__float2half(f0.z); h[3]=__float2half(f0.w);
    h[4]=__float2half(f1.x); h[5]=__float2half(f1.y);
    h[6]=__float2half(f1.z); h[7]=__float2half(f1.w);
    *(uint4*)(&g_xh[im][off]) = *(uint4*)h;
}

// ---------------- norm_k: L2 normalize only (kI, kM) — lean, high occupancy -------
// grid (TOK/32, 2); which = 2 + blockIdx.y
__global__ void __launch_bounds__(256) norm_k_kernel()
{
    const int which = 2 + blockIdx.y;
    const int tok0 = blockIdx.x * 32;
    const __half* raw = g_raw16[which];
    __half* oh = g_ph[which];

    const int warp = threadIdx.x >> 5, lane = threadIdx.x & 31;
    const int c0 = lane*8, c1 = 256 + lane*8;

    float v[4][16];
    #pragma unroll
    for (int i = 0; i < 4; i++) {
        const size_t rowb = (size_t)(tok0 + warp*4 + i)*512;
        uint4 d0 = *(const uint4*)(raw + rowb + c0);
        uint4 d1 = *(const uint4*)(raw + rowb + c1);
        __half2* hp0 = (__half2*)&d0;
        __half2* hp1 = (__half2*)&d1;
        #pragma unroll
        for (int j = 0; j < 4; j++) {
            float2 f0 = __half22float2(hp0[j]);
            float2 f1 = __half22float2(hp1[j]);
            v[i][j*2]   = f0.x; v[i][j*2+1]   = f0.y;
            v[i][8+j*2] = f1.x; v[i][8+j*2+1] = f1.y;
        }
    }
    float ss[4];
    #pragma unroll
    for (int i = 0; i < 4; i++) {
        float t = 0.f;
        #pragma unroll
        for (int j = 0; j < 16; j++) t += v[i][j]*v[i][j];
        ss[i] = t;
    }
    #pragma unroll
    for (int o = 16; o; o >>= 1) {
        #pragma unroll
        for (int i = 0; i < 4; i++)
            ss[i] += __shfl_xor_sync(0xFFFFFFFFu, ss[i], o);
    }
    #pragma unroll
    for (int i = 0; i < 4; i++) {
        const float inv = 1.f / fmaxf(sqrtf(ss[i]), 1e-12f);
        const size_t rowb = (size_t)(tok0 + warp*4 + i)*512;
        uint4 w0, w1; __half2 h;
        #pragma unroll
        for (int j = 0; j < 4; j++) {
            h = __floats2half2_rn(v[i][j*2]*inv,   v[i][j*2+1]*inv);   ((uint32_t*)&w0)[j] = *(uint32_t*)&h;
            h = __floats2half2_rn(v[i][8+j*2]*inv, v[i][8+j*2+1]*inv); ((uint32_t*)&w1)[j] = *(uint32_t*)&h;
        }
        *(uint4*)(oh + rowb + c0) = w0;
        *(uint4*)(oh + rowb + c1) = w1;
    }
}

// ---------------- norm_q: L2 norm + fp16 plane + Gu/s2 (qI, qM) ------------------
// grid (TOK/32, 2); which = blockIdx.y
__global__ void __launch_bounds__(256) norm_q_kernel(
    const float* __restrict__ wgI, const float* __restrict__ wgM)
{
    const int which = blockIdx.y;
    const int tok0 = blockIdx.x * 32;
    const int b = tok0 >> 12;
    const __half* raw = g_raw16[which];
    __half* oh = g_ph[which];

    __shared__ float sGu[513];
    const int warp = threadIdx.x >> 5, lane = threadIdx.x & 31;
    const int c0 = lane*8, c1 = 256 + lane*8;

    float wgv[16];
    {
        const float* wg = which ? wgM : wgI;
        #pragma unroll
        for (int j = 0; j < 8; j++) {
            wgv[j]   = __ldg(&wg[c0 + j]);
            wgv[8+j] = __ldg(&wg[c1 + j]);
        }
        for (int c = threadIdx.x; c < 513; c += 256) sGu[c] = 0.f;
        __syncthreads();
    }

    float v[4][16];
    #pragma unroll
    for (int i = 0; i < 4; i++) {
        const size_t rowb = (size_t)(tok0 + warp*4 + i)*512;
        uint4 d0 = *(const uint4*)(raw + rowb + c0);
        uint4 d1 = *(const uint4*)(raw + rowb + c1);
        __half2* hp0 = (__half2*)&d0;
        __half2* hp1 = (__half2*)&d1;
        #pragma unroll
        for (int j = 0; j < 4; j++) {
            float2 f0 = __half22float2(hp0[j]);
            float2 f1 = __half22float2(hp1[j]);
            v[i][j*2]   = f0.x; v[i][j*2+1]   = f0.y;
            v[i][8+j*2] = f1.x; v[i][8+j*2+1] = f1.y;
        }
    }

    float ss[4];
    #pragma unroll
    for (int i = 0; i < 4; i++) {
        float t = 0.f;
        #pragma unroll
        for (int j = 0; j < 16; j++) t += v[i][j]*v[i][j];
        ss[i] = t;
    }
    #pragma unroll
    for (int o = 16; o; o >>= 1) {
        #pragma unroll
        for (int i = 0; i < 4; i++)
            ss[i] += __shfl_xor_sync(0xFFFFFFFFu, ss[i], o);
    }
    #pragma unroll
    for (int i = 0; i < 4; i++) {
        const float inv = 1.f / fmaxf(sqrtf(ss[i]), 1e-12f);
        #pragma unroll
        for (int j = 0; j < 16; j++) v[i][j] *= inv;
    }

    #pragma unroll
    for (int i = 0; i < 4; i++) {
        const size_t rowb = (size_t)(tok0 + warp*4 + i)*512;
        uint4 w0, w1; __half2 h;
        #pragma unroll
        for (int j = 0; j < 4; j++) {
            h = __floats2half2_rn(v[i][j*2],   v[i][j*2+1]);   ((uint32_t*)&w0)[j] = *(uint32_t*)&h;
            h = __floats2half2_rn(v[i][8+j*2], v[i][8+j*2+1]); ((uint32_t*)&w1)[j] = *(uint32_t*)&h;
        }
        *(uint4*)(oh + rowb + c0) = w0;
        *(uint4*)(oh + rowb + c1) = w1;
    }

    float sp[4];
    #pragma unroll
    for (int i = 0; i < 4; i++) {
        float t = 0.f;
        #pragma unroll
        for (int j = 0; j < 16; j++) t += v[i][j]*wgv[j];
        sp[i] = t;
    }
    #pragma unroll
    for (int o = 16; o; o >>= 1) {
        #pragma unroll
        for (int i = 0; i < 4; i++)
            sp[i] += __shfl_xor_sync(0xFFFFFFFFu, sp[i], o);
    }
    #pragma unroll
    for (int j = 0; j < 8; j++) {
        float g0 = sp[0]*v[0][j]   + sp[1]*v[1][j]   + sp[2]*v[2][j]   + sp[3]*v[3][j];
        float g1 = sp[0]*v[0][8+j] + sp[1]*v[1][8+j] + sp[2]*v[2][8+j] + sp[3]*v[3][8+j];
        atomicAdd(&sGu[c0 + j], g0);
        atomicAdd(&sGu[c1 + j], g1);
    }
    if (lane == 0)
        atomicAdd(&sGu[512], sp[0]*sp[0] + sp[1]*sp[1] + sp[2]*sp[2] + sp[3]*sp[3]);
    __syncthreads();
    float* accG = g_acc + ((size_t)b*2 + which)*513;
    for (int c = threadIdx.x; c < 513; c += 256) atomicAdd(&accG[c], sGu[c]);
}

// ---------------- setup: W^T fp16, f_w^T, zero acc, cvec ----------------
__global__ void setup_kernel(const float* __restrict__ wqI, const float* __restrict__ wqM,
                             const float* __restrict__ wkI, const float* __restrict__ wkM,
                             const float* __restrict__ fw,
                             const float* __restrict__ b1, const float* __restrict__ b2,
                             const float* __restrict__ b3, const float* __restrict__ b4,
                             const float* __restrict__ fb)
{
    if (blockIdx.x >= 4642) {
        // cvec: one column per block
        int c = blockIdx.x - 4642, t = threadIdx.x;
        float p = 0.f;
        for (int e = t; e < DD; e += 256)
            p += (b1[e] + b2[e] + b3[e] + b4[e]) * fw[(size_t)e*TD + c];
        #pragma unroll
        for (int o = 16; o; o >>= 1) p += __shfl_xor_sync(0xFFFFFFFFu, p, o);
        __shared__ float sp[8];
        if ((t & 31) == 0) sp[t >> 5] = p;
        __syncthreads();
        if (t == 0) {
            float s = fb[c];
            #pragma unroll
            for (int w = 0; w < 8; w++) s += sp[w];
            g_cvec[c] = s;
        }
        return;
    }
    int idx = blockIdx.x*256 + threadIdx.x;
    if (idx < 4*DD*DD) {
        int m = idx >> 18, r = idx & (DD*DD - 1);
        int n = r >> 9, k = r & 511;
        const float* W = (m==0)?wqI:(m==1)?wqM:(m==2)?wkI:wkM;
        g_Wth[m][r] = __float2half(W[(size_t)k*DD + n]);
    } else if ((idx -= 4*DD*DD) < TD*DD) {
        int n = idx >> 9, e = idx & 511;
        g_fwT[idx] = fw[(size_t)e*TD + n];
    } else if ((idx -= TD*DD) < BB*2*513) {
        g_acc[idx] = 0.f;
    }
}

// ---------------- PFt = (p_i @ f_w)^T  (parallel: 256 CTAs) ----------------
// grid (16, 4, 4): x = row tile (32 rows of p), y = matrix, z = col tile (64 n)
__global__ void __launch_bounds__(256) pf_kernel(
    const float* __restrict__ p1, const float* __restrict__ p2,
    const float* __restrict__ p3, const float* __restrict__ p4,
    const float* __restrict__ fw)
{
    const float* P[4] = {p1, p2, p3, p4};
    const float* p = P[blockIdx.y];
    float* out = g_PFt[blockIdx.y];
    const int r0 = blockIdx.x * 32;
    const int n0 = blockIdx.z * 64;

    __shared__ float sP[32][36];   // p rows tile, padded
    __shared__ float sF[32][64];   // fw tile
    const int warp = threadIdx.x >> 5, lane = threadIdx.x & 31;

    float acc[4][2];
    #pragma unroll
    for (int i = 0; i < 4; i++) { acc[i][0] = 0.f; acc[i][1] = 0.f; }

    for (int e0 = 0; e0 < DD; e0 += 32) {
        {
            int r = threadIdx.x >> 3, e4 = threadIdx.x & 7;
            *(float4*)&sP[r][e4*4] = *(const float4*)(p + (size_t)(r0 + r)*DD + e0 + e4*4);
        }
        #pragma unroll
        for (int it = 0; it < 2; it++) {
            int v = threadIdx.x + it*256;
            int e = v >> 4, f4 = v & 15;
            *(float4*)&sF[e][f4*4] = *(const float4*)(fw + (size_t)(e0 + e)*TD + n0 + f4*4);
        }
        __syncthreads();
        #pragma unroll
        for (int kk = 0; kk < 32; kk++) {
            float w0 = sF[kk][lane], w1 = sF[kk][lane + 32];
            #pragma unroll
            for (int i = 0; i < 4; i++) {
                float a = sP[4*warp + i][kk];
                acc[i][0] += a * w0;
                acc[i][1] += a * w1;
            }
        }
        __syncthreads();
    }
    #pragma unroll
    for (int i = 0; i < 4; i++) {
        out[(size_t)(n0 + lane)*DD      + r0 + 4*warp + i] = acc[i][0];
        out[(size_t)(n0 + lane + 32)*DD + r0 + 4*warp + i] = acc[i][1];
    }
}

// ---------------- combined weights Wc^T fp16 ----------------
// K segs (2048): [0,512)=kI, [512,1024)=kM, [1024,1536)=qI (f_w), [1536,2048)=qM (f_w)
__global__ void combine_kernel()
{
    int n = blockIdx.x, b = blockIdx.y, t = threadIdx.x;
    const float* acc = g_acc + (size_t)b*2*513;
    float nI = fmaxf(SCALE_F * sqrtf(acc[512]),       1e-12f);
    float nM = fmaxf(SCALE_F * sqrtf(acc[513 + 512]), 1e-12f);
    for (int k = t; k < 2048; k += 256) {
        float v;
        if (k < 1024) {
            int kk = k & 511;
            float GI = SCALE_F * acc[kk] / nI;
            float GM = SCALE_F * acc[513 + kk] / nM;
            if (k < 512) v = GI*g_PFt[0][(size_t)n*DD+kk] + GM*g_PFt[3][(size_t)n*DD+kk];
            else         v = GI*g_PFt[1][(size_t)n*DD+kk] + GM*g_PFt[2][(size_t)n*DD+kk];
        } else {
            v = g_fwT[(size_t)n*DD + (k & 511)];
        }
        g_Wch[b][(size_t)n*2048 + k] = __float2half(v);
    }
}

// ---------------- launch ----------------
extern "C" void kernel_launch(void* const* d_in, const int* in_sizes, int n_in,
                              void* d_out, int out_size)
{
    const float* xI  = (const float*)d_in[0];
    const float* xM  = (const float*)d_in[1];
    const float* wqI = (const float*)d_in[2];
    const float* bqI = (const float*)d_in[3];
    const float* wkI = (const float*)d_in[4];
    const float* bkI = (const float*)d_in[5];
    const float* wqM = (const float*)d_in[6];
    const float* bqM = (const float*)d_in[7];
    const float* wkM = (const float*)d_in[8];
    const float* bkM = (const float*)d_in[9];
    const float* wgI = (const float*)d_in[10];
    const float* wgM = (const float*)d_in[11];
    const float* p1w = (const float*)d_in[12];
    const float* p1b = (const float*)d_in[13];
    const float* p2w = (const float*)d_in[14];
    const float* p2b = (const float*)d_in[15];
    const float* p3w = (const float*)d_in[16];
    const float* p3b = (const float*)d_in[17];
    const float* p4w = (const float*)d_in[18];
    const float* p4b = (const float*)d_in[19];
    const float* fw  = (const float*)d_in[20];
    const float* fb  = (const float*)d_in[21];
    float* out = (float*)d_out;

    static cudaStream_t s_pf = nullptr;
    static cudaEvent_t e_fork = nullptr, e_pf = nullptr;
    if (s_pf == nullptr) {
        cudaStreamCreateWithFlags(&s_pf, cudaStreamNonBlocking);
        cudaEventCreateWithFlags(&e_fork, cudaEventDisableTiming);
        cudaEventCreateWithFlags(&e_pf, cudaEventDisableTiming);
        cudaFuncSetAttribute(mma_gemm<0>, cudaFuncAttributeMaxDynamicSharedMemorySize, SMEM_TOTAL);
        cudaFuncSetAttribute(mma_gemm<1>, cudaFuncAttributeMaxDynamicSharedMemorySize, SMEM_TOTAL);
    }

    // fork: pf runs on side stream, overlapped with xconv/gemm0/norm
    cudaEventRecord(e_fork, 0);
    cudaStreamWaitEvent(s_pf, e_fork, 0);
    pf_kernel<<<dim3(16, 4, 4), 256, 0, s_pf>>>(p1w, p2w, p3w, p4w, fw);
    cudaEventRecord(e_pf, s_pf);

    setup_kernel<<<4642 + TD, 256>>>(wqI, wqM, wkI, wkM, fw, p1b, p2b, p3b, p4b, fb);
    xconv_kernel<<<dim3(TOK*DD/(256*8), 2), 256>>>(xI, xM);
    mma_gemm<0><<<4096, 256, SMEM_TOTAL>>>(bqI, bqM, bkI, bkM, nullptr);
    norm_k_kernel<<<dim3(TOK/32, 2), 256>>>();
    norm_q_kernel<<<dim3(TOK/32, 2), 256>>>(wgI, wgM);

    // join: combine needs pf (g_PFt) + norm_q (g_acc)
    cudaStreamWaitEvent(0, e_pf, 0);
    combine_kernel<<<dim3(TD, BB), 256>>>();
    mma_gemm<1><<<512, 256, SMEM_TOTAL>>>(bqI, bqM, bkI, bkM, out);
}

// round 17
// speedup vs baseline: 1.0817x; 1.0147x over previous
#include <cuda_runtime.h>
#include <cuda_fp16.h>
#include <math.h>
#include <stdint.h>

#define BB 8
#define NN 4096
#define DD 512
#define TD 256
#define TOK (BB*NN)
#define SCALE_F 0.0625f

// ---------------- static scratch ----------------
__device__ __align__(16) __half g_xh[2][(size_t)TOK*DD];     // x fp16 (I, M)
__device__ __align__(16) __half g_raw16[4][(size_t)TOK*DD];  // proj out + bias, fp16
__device__ __align__(16) __half g_ph[4][(size_t)TOK*DD];     // normalized q/k fp16 [qI,qM,kI,kM]
__device__ __align__(16) __half g_Wth[4][DD*DD];             // W^T fp16 [mat][n][k]
__device__ __align__(16) __half g_Wch[BB][TD*2048];          // combined W^T fp16 [b][n][k]
__device__ float g_fwT[TD*DD];                               // f_w^T [n][e]
__device__ float g_PFt[4][TD*DD];                            // (p_i@f_w)^T [n][k]
__device__ float g_acc[BB*2*513];
__device__ float g_cvec[TD];

// ---------------- helpers ----------------
__device__ __forceinline__ uint32_t smem_u32(const void* p) {
    uint32_t a;
    asm("{ .reg .u64 t; cvta.to.shared.u64 t, %1; cvt.u32.u64 %0, t; }" : "=r"(a) : "l"(p));
    return a;
}
__device__ __forceinline__ void cp16(uint32_t s, const void* g) {
    asm volatile("cp.async.cg.shared.global [%0], [%1], 16;" :: "r"(s), "l"(g));
}
__device__ __forceinline__ void cp_commit() { asm volatile("cp.async.commit_group;"); }
__device__ __forceinline__ void cp_wait1()  { asm volatile("cp.async.wait_group 1;"); }
__device__ __forceinline__ void cp_wait0()  { asm volatile("cp.async.wait_group 0;"); }
__device__ __forceinline__ void ldsm4(uint32_t* r, uint32_t addr) {
    asm volatile("ldmatrix.sync.aligned.m8n8.x4.shared.b16 {%0,%1,%2,%3}, [%4];"
        : "=r"(r[0]), "=r"(r[1]), "=r"(r[2]), "=r"(r[3]) : "r"(addr));
}
__device__ __forceinline__ void mma_f16(float* c, const uint32_t* a, uint32_t b0, uint32_t b1) {
    asm volatile("mma.sync.aligned.m16n8k16.row.col.f32.f16.f16.f32 "
        "{%0,%1,%2,%3}, {%4,%5,%6,%7}, {%8,%9}, {%0,%1,%2,%3};"
        : "+f"(c[0]), "+f"(c[1]), "+f"(c[2]), "+f"(c[3])
        : "r"(a[0]), "r"(a[1]), "r"(a[2]), "r"(a[3]), "r"(b0), "r"(b1));
}

// SMEM per buffer: A 16KB + B 16KB = 32KB; ring of 3 = 96KB
#define BUFSZ 32768
#define SMEM_TOTAL 98304

// ---------------- MMA GEMM (MODE 0 = proj -> raw16 (+bias); MODE 1 = final -> out) ----
// MODE 0 grid: 4096 flat; bx&3=which, (bx>>2)&3=ntile, bx>>4=tokblk (A sharers adjacent)
// MODE 1 grid: 512 flat;  bx&1=ntile, bx>>1=tokblk
template<int MODE>
__global__ void __launch_bounds__(256) mma_gemm(
    const float* __restrict__ bqI, const float* __restrict__ bqM,
    const float* __restrict__ bkI, const float* __restrict__ bkM,
    float* __restrict__ outp)
{
    extern __shared__ char smem[];
    const uint32_t sb = smem_u32(smem);
    __shared__ float sbias[128];

    const int tid = threadIdx.x, wid = tid >> 5, lane = tid & 31;
    const int bx = blockIdx.x;
    const int which = (MODE == 0) ? (bx & 3) : 0;
    const int n0    = (MODE == 0) ? (((bx >> 2) & 3) * 128) : ((bx & 1) * 128);
    const int tok0  = (MODE == 0) ? ((bx >> 4) * 128) : ((bx >> 1) * 128);
    const int batch = tok0 >> 12;
    const int NC = (MODE == 0) ? 8 : 32;

    if (MODE == 0) {
        const float* bias = (which==0)?bqI:(which==1)?bqM:(which==2)?bkI:bkM;
        if (tid < 128) sbias[tid] = bias[n0 + tid];
    } else {
        if (tid < 128) sbias[tid] = g_cvec[n0 + tid];
    }

    const int xsel = which & 1;

    // ---- issue chunk c (Kc=64) into ring buffer via cp.async ----
    auto issue = [&](int c, int buf) {
        uint32_t abase = sb + buf*BUFSZ;
        uint32_t bbase = abase + 16384;
        // A: 128 rows x 64 halves (8 x 16B per row)
        #pragma unroll
        for (int it = 0; it < 4; it++) {
            int v = it*256 + tid;
            int r = v >> 3, u = v & 7;
            const __half* src;
            if (MODE == 0) {
                src = g_xh[xsel] + (size_t)(tok0 + r)*512 + c*64 + u*8;
            } else {
                int mat = (c >> 3) ^ 2;     // k-segs: kI,kM,qI,qM -> mats 2,3,0,1
                src = g_ph[mat] + (size_t)(tok0 + r)*512 + (c & 7)*64 + u*8;
            }
            cp16(abase + r*128 + ((u ^ (r & 7)) << 4), src);
        }
        // B: 128 n-rows x 64 halves
        #pragma unroll
        for (int it = 0; it < 4; it++) {
            int v = it*256 + tid;
            int r = v >> 3, u = v & 7;
            const __half* src;
            if (MODE == 0) {
                src = g_Wth[which] + (size_t)(n0 + r)*512 + c*64 + u*8;
            } else {
                src = g_Wch[batch] + (size_t)(n0 + r)*2048 + c*64 + u*8;
            }
            cp16(bbase + r*128 + ((u ^ (r & 7)) << 4), src);
        }
        cp_commit();
    };

    float acc[2][8][4];
    #pragma unroll
    for (int mt = 0; mt < 2; mt++)
        #pragma unroll
        for (int nt = 0; nt < 8; nt++)
            #pragma unroll
            for (int e = 0; e < 4; e++) acc[mt][nt][e] = 0.f;

    const int wm = wid >> 1, wn = wid & 1;      // warps 4x2 -> 32m x 64n per warp
    const int mwb = wm * 32, nwb = wn * 64;

    issue(0, 0);
    issue(1, 1);

    int buf = 0;
    for (int c = 0; c < NC; c++) {
        if (c < NC - 1) cp_wait1(); else cp_wait0();
        __syncthreads();
        // overwrite the buffer consumed at chunk c-1 (barrier above proves all
        // warps are done with it)
        if (c + 2 < NC) {
            int nb = buf + 2; if (nb >= 3) nb -= 3;
            issue(c + 2, nb);
        }
        uint32_t abase = sb + buf*BUFSZ;
        uint32_t bbase = abase + 16384;

        #pragma unroll
        for (int k16 = 0; k16 < 4; k16++) {
            uint32_t ah[2][4], bh[4][4];
            #pragma unroll
            for (int mt = 0; mt < 2; mt++) {
                int row = mwb + mt*16 + (lane & 15);
                int kb  = k16*2 + (lane >> 4);
                ldsm4(ah[mt], abase + row*128 + ((kb ^ (row & 7)) << 4));
            }
            #pragma unroll
            for (int bt = 0; bt < 4; bt++) {
                int row = nwb + bt*16 + ((lane >> 4) << 3) + (lane & 7);
                int kb  = k16*2 + ((lane >> 3) & 1);
                ldsm4(bh[bt], bbase + row*128 + ((kb ^ (row & 7)) << 4));
            }
            #pragma unroll
            for (int mt = 0; mt < 2; mt++)
                #pragma unroll
                for (int nt = 0; nt < 8; nt++) {
                    int bt = nt >> 1, s = (nt & 1) * 2;
                    mma_f16(acc[mt][nt], ah[mt], bh[bt][s], bh[bt][s+1]);
                }
        }
        if (++buf >= 3) buf = 0;
    }

    // ---- epilogue ----
    #pragma unroll
    for (int mt = 0; mt < 2; mt++) {
        int row = tok0 + mwb + mt*16 + (lane >> 2);
        #pragma unroll
        for (int nt = 0; nt < 8; nt++) {
            int col = n0 + nwb + nt*8 + 2*(lane & 3);
            float b0 = sbias[col - n0], b1 = sbias[col - n0 + 1];
            if (MODE == 0) {
                __half* o = g_raw16[which];
                *(__half2*)(o + (size_t)row*512 + col) =
                    __floats2half2_rn(acc[mt][nt][0] + b0, acc[mt][nt][1] + b1);
                *(__half2*)(o + (size_t)(row+8)*512 + col) =
                    __floats2half2_rn(acc[mt][nt][2] + b0, acc[mt][nt][3] + b1);
            } else {
                *(float2*)(outp + (size_t)row*256 + col) =
                    make_float2(acc[mt][nt][0] + b0, acc[mt][nt][1] + b1);
                *(float2*)(outp + (size_t)(row+8)*256 + col) =
                    make_float2(acc[mt][nt][2] + b0, acc[mt][nt][3] + b1);
            }
        }
    }
}

// ---------------- x -> fp16 ----------------
__global__ void xconv_kernel(const float* __restrict__ xI, const float* __restrict__ xM)
{
    const int im = blockIdx.y;
    const float* x = im ? xM : xI;
    size_t off = ((size_t)blockIdx.x*256 + threadIdx.x) * 8;
    float4 f0 = *(const float4*)(x + off);
    float4 f1 = *(const float4*)(x + off + 4);
    __half h[8];
    h[0]=__float2half(f0.x); h[1]=__float2half(f0.y);
    h[2]=__float2half(f0.z); h[3]=__float2half(f0.w);
    h[4]=__float2half(f1.x); h[5]=__float2half(f1.y);
    h[6]=__float2half(f1.z); h[7]=__float2half(f1.w);
    *(uint4*)(&g_xh[im][off]) = *(uint4*)h;
}

// ---------------- norm_k: L2 normalize only (kI, kM) — lean, high occupancy -------
// grid (TOK/32, 2); which = 2 + blockIdx.y
__global__ void __launch_bounds__(256) norm_k_kernel()
{
    const int which = 2 + blockIdx.y;
    const int tok0 = blockIdx.x * 32;
    const __half* raw = g_raw16[which];
    __half* oh = g_ph[which];

    const int warp = threadIdx.x >> 5, lane = threadIdx.x & 31;
    const int c0 = lane*8, c1 = 256 + lane*8;

    float v[4][16];
    #pragma unroll
    for (int i = 0; i < 4; i++) {
        const size_t rowb = (size_t)(tok0 + warp*4 + i)*512;
        uint4 d0 = *(const uint4*)(raw + rowb + c0);
        uint4 d1 = *(const uint4*)(raw + rowb + c1);
        __half2* hp0 = (__half2*)&d0;
        __half2* hp1 = (__half2*)&d1;
        #pragma unroll
        for (int j = 0; j < 4; j++) {
            float2 f0 = __half22float2(hp0[j]);
            float2 f1 = __half22float2(hp1[j]);
            v[i][j*2]   = f0.x; v[i][j*2+1]   = f0.y;
            v[i][8+j*2] = f1.x; v[i][8+j*2+1] = f1.y;
        }
    }
    float ss[4];
    #pragma unroll
    for (int i = 0; i < 4; i++) {
        float t = 0.f;
        #pragma unroll
        for (int j = 0; j < 16; j++) t += v[i][j]*v[i][j];
        ss[i] = t;
    }
    #pragma unroll
    for (int o = 16; o; o >>= 1) {
        #pragma unroll
        for (int i = 0; i < 4; i++)
            ss[i] += __shfl_xor_sync(0xFFFFFFFFu, ss[i], o);
    }
    #pragma unroll
    for (int i = 0; i < 4; i++) {
        const float inv = 1.f / fmaxf(sqrtf(ss[i]), 1e-12f);
        const size_t rowb = (size_t)(tok0 + warp*4 + i)*512;
        uint4 w0, w1; __half2 h;
        #pragma unroll
        for (int j = 0; j < 4; j++) {
            h = __floats2half2_rn(v[i][j*2]*inv,   v[i][j*2+1]*inv);   ((uint32_t*)&w0)[j] = *(uint32_t*)&h;
            h = __floats2half2_rn(v[i][8+j*2]*inv, v[i][8+j*2+1]*inv); ((uint32_t*)&w1)[j] = *(uint32_t*)&h;
        }
        *(uint4*)(oh + rowb + c0) = w0;
        *(uint4*)(oh + rowb + c1) = w1;
    }
}

// ---------------- norm_q: L2 norm + fp16 plane + Gu/s2 (qI, qM) ------------------
// grid (TOK/32, 2); which = blockIdx.y
__global__ void __launch_bounds__(256) norm_q_kernel(
    const float* __restrict__ wgI, const float* __restrict__ wgM)
{
    const int which = blockIdx.y;
    const int tok0 = blockIdx.x * 32;
    const int b = tok0 >> 12;
    const __half* raw = g_raw16[which];
    __half* oh = g_ph[which];

    __shared__ float sGu[513];
    const int warp = threadIdx.x >> 5, lane = threadIdx.x & 31;
    const int c0 = lane*8, c1 = 256 + lane*8;

    float wgv[16];
    {
        const float* wg = which ? wgM : wgI;
        #pragma unroll
        for (int j = 0; j < 8; j++) {
            wgv[j]   = __ldg(&wg[c0 + j]);
            wgv[8+j] = __ldg(&wg[c1 + j]);
        }
        for (int c = threadIdx.x; c < 513; c += 256) sGu[c] = 0.f;
        __syncthreads();
    }

    float v[4][16];
    #pragma unroll
    for (int i = 0; i < 4; i++) {
        const size_t rowb = (size_t)(tok0 + warp*4 + i)*512;
        uint4 d0 = *(const uint4*)(raw + rowb + c0);
        uint4 d1 = *(const uint4*)(raw + rowb + c1);
        __half2* hp0 = (__half2*)&d0;
        __half2* hp1 = (__half2*)&d1;
        #pragma unroll
        for (int j = 0; j < 4; j++) {
            float2 f0 = __half22float2(hp0[j]);
            float2 f1 = __half22float2(hp1[j]);
            v[i][j*2]   = f0.x; v[i][j*2+1]   = f0.y;
            v[i][8+j*2] = f1.x; v[i][8+j*2+1] = f1.y;
        }
    }

    float ss[4];
    #pragma unroll
    for (int i = 0; i < 4; i++) {
        float t = 0.f;
        #pragma unroll
        for (int j = 0; j < 16; j++) t += v[i][j]*v[i][j];
        ss[i] = t;
    }
    #pragma unroll
    for (int o = 16; o; o >>= 1) {
        #pragma unroll
        for (int i = 0; i < 4; i++)
            ss[i] += __shfl_xor_sync(0xFFFFFFFFu, ss[i], o);
    }
    #pragma unroll
    for (int i = 0; i < 4; i++) {
        const float inv = 1.f / fmaxf(sqrtf(ss[i]), 1e-12f);
        #pragma unroll
        for (int j = 0; j < 16; j++) v[i][j] *= inv;
    }

    #pragma unroll
    for (int i = 0; i < 4; i++) {
        const size_t rowb = (size_t)(tok0 + warp*4 + i)*512;
        uint4 w0, w1; __half2 h;
        #pragma unroll
        for (int j = 0; j < 4; j++) {
            h = __floats2half2_rn(v[i][j*2],   v[i][j*2+1]);   ((uint32_t*)&w0)[j] = *(uint32_t*)&h;
            h = __floats2half2_rn(v[i][8+j*2], v[i][8+j*2+1]); ((uint32_t*)&w1)[j] = *(uint32_t*)&h;
        }
        *(uint4*)(oh + rowb + c0) = w0;
        *(uint4*)(oh + rowb + c1) = w1;
    }

    float sp[4];
    #pragma unroll
    for (int i = 0; i < 4; i++) {
        float t = 0.f;
        #pragma unroll
        for (int j = 0; j < 16; j++) t += v[i][j]*wgv[j];
        sp[i] = t;
    }
    #pragma unroll
    for (int o = 16; o; o >>= 1) {
        #pragma unroll
        for (int i = 0; i < 4; i++)
            sp[i] += __shfl_xor_sync(0xFFFFFFFFu, sp[i], o);
    }
    #pragma unroll
    for (int j = 0; j < 8; j++) {
        float g0 = sp[0]*v[0][j]   + sp[1]*v[1][j]   + sp[2]*v[2][j]   + sp[3]*v[3][j];
        float g1 = sp[0]*v[0][8+j] + sp[1]*v[1][8+j] + sp[2]*v[2][8+j] + sp[3]*v[3][8+j];
        atomicAdd(&sGu[c0 + j], g0);
        atomicAdd(&sGu[c1 + j], g1);
    }
    if (lane == 0)
        atomicAdd(&sGu[512], sp[0]*sp[0] + sp[1]*sp[1] + sp[2]*sp[2] + sp[3]*sp[3]);
    __syncthreads();
    float* accG = g_acc + ((size_t)b*2 + which)*513;
    for (int c = threadIdx.x; c < 513; c += 256) atomicAdd(&accG[c], sGu[c]);
}

// ---------------- setup: W^T fp16, f_w^T, zero acc, cvec ----------------
__global__ void setup_kernel(const float* __restrict__ wqI, const float* __restrict__ wqM,
                             const float* __restrict__ wkI, const float* __restrict__ wkM,
                             const float* __restrict__ fw,
                             const float* __restrict__ b1, const float* __restrict__ b2,
                             const float* __restrict__ b3, const float* __restrict__ b4,
                             const float* __restrict__ fb)
{
    if (blockIdx.x >= 4642) {
        // cvec: one column per block
        int c = blockIdx.x - 4642, t = threadIdx.x;
        float p = 0.f;
        for (int e = t; e < DD; e += 256)
            p += (b1[e] + b2[e] + b3[e] + b4[e]) * fw[(size_t)e*TD + c];
        #pragma unroll
        for (int o = 16; o; o >>= 1) p += __shfl_xor_sync(0xFFFFFFFFu, p, o);
        __shared__ float sp[8];
        if ((t & 31) == 0) sp[t >> 5] = p;
        __syncthreads();
        if (t == 0) {
            float s = fb[c];
            #pragma unroll
            for (int w = 0; w < 8; w++) s += sp[w];
            g_cvec[c] = s;
        }
        return;
    }
    int idx = blockIdx.x*256 + threadIdx.x;
    if (idx < 4*DD*DD) {
        int m = idx >> 18, r = idx & (DD*DD - 1);
        int n = r >> 9, k = r & 511;
        const float* W = (m==0)?wqI:(m==1)?wqM:(m==2)?wkI:wkM;
        g_Wth[m][r] = __float2half(W[(size_t)k*DD + n]);
    } else if ((idx -= 4*DD*DD) < TD*DD) {
        int n = idx >> 9, e = idx & 511;
        g_fwT[idx] = fw[(size_t)e*TD + n];
    } else if ((idx -= TD*DD) < BB*2*513) {
        g_acc[idx] = 0.f;
    }
}

// ---------------- PFt = (p_i @ f_w)^T  (parallel: 256 CTAs) ----------------
// grid (16, 4, 4): x = row tile (32 rows of p), y = matrix, z = col tile (64 n)
__global__ void __launch_bounds__(256) pf_kernel(
    const float* __restrict__ p1, const float* __restrict__ p2,
    const float* __restrict__ p3, const float* __restrict__ p4,
    const float* __restrict__ fw)
{
    const float* P[4] = {p1, p2, p3, p4};
    const float* p = P[blockIdx.y];
    float* out = g_PFt[blockIdx.y];
    const int r0 = blockIdx.x * 32;
    const int n0 = blockIdx.z * 64;

    __shared__ float sP[32][36];   // p rows tile, padded
    __shared__ float sF[32][64];   // fw tile
    const int warp = threadIdx.x >> 5, lane = threadIdx.x & 31;

    float acc[4][2];
    #pragma unroll
    for (int i = 0; i < 4; i++) { acc[i][0] = 0.f; acc[i][1] = 0.f; }

    for (int e0 = 0; e0 < DD; e0 += 32) {
        {
            int r = threadIdx.x >> 3, e4 = threadIdx.x & 7;
            *(float4*)&sP[r][e4*4] = *(const float4*)(p + (size_t)(r0 + r)*DD + e0 + e4*4);
        }
        #pragma unroll
        for (int it = 0; it < 2; it++) {
            int v = threadIdx.x + it*256;
            int e = v >> 4, f4 = v & 15;
            *(float4*)&sF[e][f4*4] = *(const float4*)(fw + (size_t)(e0 + e)*TD + n0 + f4*4);
        }
        __syncthreads();
        #pragma unroll
        for (int kk = 0; kk < 32; kk++) {
            float w0 = sF[kk][lane], w1 = sF[kk][lane + 32];
            #pragma unroll
            for (int i = 0; i < 4; i++) {
                float a = sP[4*warp + i][kk];
                acc[i][0] += a * w0;
                acc[i][1] += a * w1;
            }
        }
        __syncthreads();
    }
    #pragma unroll
    for (int i = 0; i < 4; i++) {
        out[(size_t)(n0 + lane)*DD      + r0 + 4*warp + i] = acc[i][0];
        out[(size_t)(n0 + lane + 32)*DD + r0 + 4*warp + i] = acc[i][1];
    }
}

// ---------------- combined weights Wc^T fp16 ----------------
// K segs (2048): [0,512)=kI, [512,1024)=kM, [1024,1536)=qI (f_w), [1536,2048)=qM (f_w)
__global__ void combine_kernel()
{
    int n = blockIdx.x, b = blockIdx.y, t = threadIdx.x;
    const float* acc = g_acc + (size_t)b*2*513;
    float nI = fmaxf(SCALE_F * sqrtf(acc[512]),       1e-12f);
    float nM = fmaxf(SCALE_F * sqrtf(acc[513 + 512]), 1e-12f);
    for (int k = t; k < 2048; k += 256) {
        float v;
        if (k < 1024) {
            int kk = k & 511;
            float GI = SCALE_F * acc[kk] / nI;
            float GM = SCALE_F * acc[513 + kk] / nM;
            if (k < 512) v = GI*g_PFt[0][(size_t)n*DD+kk] + GM*g_PFt[3][(size_t)n*DD+kk];
            else         v = GI*g_PFt[1][(size_t)n*DD+kk] + GM*g_PFt[2][(size_t)n*DD+kk];
        } else {
            v = g_fwT[(size_t)n*DD + (k & 511)];
        }
        g_Wch[b][(size_t)n*2048 + k] = __float2half(v);
    }
}

// ---------------- launch ----------------
extern "C" void kernel_launch(void* const* d_in, const int* in_sizes, int n_in,
                              void* d_out, int out_size)
{
    const float* xI  = (const float*)d_in[0];
    const float* xM  = (const float*)d_in[1];
    const float* wqI = (const float*)d_in[2];
    const float* bqI = (const float*)d_in[3];
    const float* wkI = (const float*)d_in[4];
    const float* bkI = (const float*)d_in[5];
    const float* wqM = (const float*)d_in[6];
    const float* bqM = (const float*)d_in[7];
    const float* wkM = (const float*)d_in[8];
    const float* bkM = (const float*)d_in[9];
    const float* wgI = (const float*)d_in[10];
    const float* wgM = (const float*)d_in[11];
    const float* p1w = (const float*)d_in[12];
    const float* p1b = (const float*)d_in[13];
    const float* p2w = (const float*)d_in[14];
    const float* p2b = (const float*)d_in[15];
    const float* p3w = (const float*)d_in[16];
    const float* p3b = (const float*)d_in[17];
    const float* p4w = (const float*)d_in[18];
    const float* p4b = (const float*)d_in[19];
    const float* fw  = (const float*)d_in[20];
    const float* fb  = (const float*)d_in[21];
    float* out = (float*)d_out;

    static cudaStream_t s_pf = nullptr, s_set = nullptr;
    static cudaEvent_t e_fork = nullptr, e_pf = nullptr, e_set = nullptr;
    static cudaEvent_t e_nq = nullptr, e_cmb = nullptr;
    if (s_pf == nullptr) {
        cudaStreamCreateWithFlags(&s_pf, cudaStreamNonBlocking);
        cudaStreamCreateWithFlags(&s_set, cudaStreamNonBlocking);
        cudaEventCreateWithFlags(&e_fork, cudaEventDisableTiming);
        cudaEventCreateWithFlags(&e_pf, cudaEventDisableTiming);
        cudaEventCreateWithFlags(&e_set, cudaEventDisableTiming);
        cudaEventCreateWithFlags(&e_nq, cudaEventDisableTiming);
        cudaEventCreateWithFlags(&e_cmb, cudaEventDisableTiming);
        cudaFuncSetAttribute(mma_gemm<0>, cudaFuncAttributeMaxDynamicSharedMemorySize, SMEM_TOTAL);
        cudaFuncSetAttribute(mma_gemm<1>, cudaFuncAttributeMaxDynamicSharedMemorySize, SMEM_TOTAL);
    }

    // ---- fork: pf and setup run on side streams ----
    cudaEventRecord(e_fork, 0);
    cudaStreamWaitEvent(s_pf, e_fork, 0);
    pf_kernel<<<dim3(16, 4, 4), 256, 0, s_pf>>>(p1w, p2w, p3w, p4w, fw);
    cudaEventRecord(e_pf, s_pf);

    cudaStreamWaitEvent(s_set, e_fork, 0);
    setup_kernel<<<4642 + TD, 256, 0, s_set>>>(wqI, wqM, wkI, wkM, fw,
                                               p1b, p2b, p3b, p4b, fb);
    cudaEventRecord(e_set, s_set);

    // ---- main: xconv overlaps setup; gemm0 needs both ----
    xconv_kernel<<<dim3(TOK*DD/(256*8), 2), 256>>>(xI, xM);
    cudaStreamWaitEvent(0, e_set, 0);
    mma_gemm<0><<<4096, 256, SMEM_TOTAL>>>(bqI, bqM, bkI, bkM, nullptr);

    // ---- norm_q first; combine (needs norm_q + pf) overlaps norm_k ----
    norm_q_kernel<<<dim3(TOK/32, 2), 256>>>(wgI, wgM);
    cudaEventRecord(e_nq, 0);
    cudaStreamWaitEvent(s_pf, e_nq, 0);      // s_pf already has pf done in-order
    combine_kernel<<<dim3(TD, BB), 256, 0, s_pf>>>();
    cudaEventRecord(e_cmb, s_pf);

    norm_k_kernel<<<dim3(TOK/32, 2), 256>>>();

    // ---- join: gemm1 needs norm_k (main, in-order) + combine ----
    cudaStreamWaitEvent(0, e_cmb, 0);
    mma_gemm<1><<<512, 256, SMEM_TOTAL>>>(bqI, bqM, bkI, bkM, out);
}